// round 16
// baseline (speedup 1.0000x reference)
#include <cuda_runtime.h>
#include <cuda_fp16.h>
#include <math.h>
#include <stdint.h>

// ---------------------------------------------------------------------------
// Problem constants
// ---------------------------------------------------------------------------
#define MINST 156
#define NTOK  256
#define DM    256
#define DFF   1024
#define NHEAD 8
#define DHEAD 32
#define NOBS  100
#define NLAYER 4

#define RSUM 27690
#define RP   27776            // 217 * 128
#define QKVW (3*DM)           // 768

__device__ __forceinline__ int inst_off(int m) {
    return NOBS*m + (m*(m-1))/2;
}

// ---------------------------------------------------------------------------
// Device-global scratch
// ---------------------------------------------------------------------------
__device__ float  g_X [(size_t)RP*DM];        // fp32 residual stream (packed)
__device__ __half g_Xh[(size_t)RP*DM];        // fp16 copy of X
__device__ __half g_QKVh[(size_t)RP*QKVW];    // fused Q|K|V fp16
__device__ __half g_QKV0h[(size_t)NTOK*QKVW]; // layer-0 compact QKV fp16
__device__ __half g_x0h[(size_t)NTOK*DM];     // layer-0 compact x0 fp16
__device__ __half g_Oh[(size_t)RP*DM];        // attention output fp16
__device__ __half g_Ph[(size_t)RP*DM];        // proj / ffn2 output fp16
__device__ __half g_Hh[(size_t)RP*DFF];       // ffn hidden fp16
__device__ float  g_x0[NTOK*DM];
__device__ float  g_bias[NTOK];
__device__ float  g_bqkv[NLAYER*QKVW];
__device__ int    g_pos[RP];                  // row -> token position (pad: 0)
__device__ int    g_flags[6*224];             // last-block flags (self-resetting)

// fp16 weights, transposed: Wh[N][K]  (row = output col, K-major)
__device__ __half g_WqkvH[NLAYER*(size_t)QKVW*DM];
__device__ __half g_WoH[NLAYER*(size_t)DM*DM];
__device__ __half g_W1H[NLAYER*(size_t)DFF*DM];
__device__ __half g_W2H[NLAYER*(size_t)DM*DFF];

// ---------------------------------------------------------------------------
// PTX helpers
// ---------------------------------------------------------------------------
__device__ __forceinline__ uint32_t smem_u32(const void* p) {
    uint32_t a;
    asm("{ .reg .u64 t; cvta.to.shared.u64 t, %1; cvt.u32.u64 %0, t; }"
        : "=r"(a) : "l"(p));
    return a;
}
__device__ __forceinline__ void cpa16(uint32_t sts, const void* g) {
    asm volatile("cp.async.cg.shared.global [%0], [%1], 16;" :: "r"(sts), "l"(g));
}
__device__ __forceinline__ void cpa_commit() {
    asm volatile("cp.async.commit_group;" ::: "memory");
}
template <int N> __device__ __forceinline__ void cpa_wait() {
    asm volatile("cp.async.wait_group %0;" :: "n"(N) : "memory");
}
__device__ __forceinline__ void ldm4(uint32_t* r, uint32_t a) {
    asm volatile("ldmatrix.sync.aligned.m8n8.x4.shared.b16 {%0,%1,%2,%3}, [%4];"
        : "=r"(r[0]), "=r"(r[1]), "=r"(r[2]), "=r"(r[3]) : "r"(a));
}
__device__ __forceinline__ void ldm4t(uint32_t* r, uint32_t a) {
    asm volatile("ldmatrix.sync.aligned.m8n8.x4.trans.shared.b16 {%0,%1,%2,%3}, [%4];"
        : "=r"(r[0]), "=r"(r[1]), "=r"(r[2]), "=r"(r[3]) : "r"(a));
}
__device__ __forceinline__ void mma16816(float* d, const uint32_t* a,
                                         uint32_t b0, uint32_t b1) {
    asm volatile(
        "mma.sync.aligned.m16n8k16.row.col.f32.f16.f16.f32 "
        "{%0,%1,%2,%3}, {%4,%5,%6,%7}, {%8,%9}, {%0,%1,%2,%3};"
        : "+f"(d[0]), "+f"(d[1]), "+f"(d[2]), "+f"(d[3])
        : "r"(a[0]), "r"(a[1]), "r"(a[2]), "r"(a[3]), "r"(b0), "r"(b1));
}
__device__ __forceinline__ uint32_t packh2(float x, float y) {
    __half2 t = __floats2half2_rn(x, y);
    return *reinterpret_cast<uint32_t*>(&t);
}

// ---------------------------------------------------------------------------
// Init kernels
// ---------------------------------------------------------------------------
__global__ void init_x0_kernel(const float* __restrict__ enc)
{
    int pos = blockIdx.x, c = threadIdx.x;
    float ang = (float)pos * powf(10000.f, -(float)c / 128.f);
    float pe  = (c & 1) ? cosf(ang) : sinf(ang);
    float v = enc[pos*DM + c] + pe;
    g_x0[pos*DM + c]  = v;
    g_x0h[pos*DM + c] = __float2half_rn(v);
}

__global__ void init_bias_kernel(const unsigned char* __restrict__ m)
{
    __shared__ int notf32, noti32, anynz;
    int t = threadIdx.x;
    if (t == 0) { notf32 = 0; noti32 = 0; anynz = 0; }
    __syncthreads();
    if (t < 64) {
        unsigned int w = ((const unsigned int*)m)[t];
        if (w != 0u && w != 0x3f800000u) atomicOr(&notf32, 1);
        if (w != 0u && w != 1u)          atomicOr(&noti32, 1);
    }
    if (m[t]) atomicOr(&anynz, 1);
    __syncthreads();
    bool mv;
    if (!anynz)        mv = false;
    else if (!notf32)  mv = ((const float*)m)[t] != 0.f;
    else if (!noti32)  mv = ((const int*)m)[t]   != 0;
    else               mv = m[t] != 0;
    g_bias[t] = mv ? 0.f : -1e9f;
}

__global__ void concat_bias_kernel(const float* __restrict__ bq,
                                   const float* __restrict__ bk,
                                   const float* __restrict__ bv)
{
    int l = blockIdx.x, c = threadIdx.x;
    g_bqkv[l*QKVW + c]        = bq[l*DM + c];
    g_bqkv[l*QKVW + DM + c]   = bk[l*DM + c];
    g_bqkv[l*QKVW + 2*DM + c] = bv[l*DM + c];
}

// Row -> token-position table (pad rows stay 0 from zero-init).
__global__ void pos_kernel()
{
    int m = blockIdx.x;
    int p = NOBS + m, o = inst_off(m);
    for (int pos = threadIdx.x; pos < p; pos += 256)
        g_pos[o + pos] = pos;
}

// ---------------------------------------------------------------------------
// Fused weight conversion, all layers & matrices in ONE launch.
// ---------------------------------------------------------------------------
__global__ void convw_all_kernel(
    const float* __restrict__ Wq, const float* __restrict__ Wk,
    const float* __restrict__ Wv, const float* __restrict__ Wo,
    const float* __restrict__ W1, const float* __restrict__ W2)
{
    int z = blockIdx.z;
    int l = z / 6, w = z % 6;
    const float* src; __half* dst; int K, N;
    switch (w) {
        case 0: src = Wq + (size_t)l*DM*DM;  dst = g_WqkvH + (size_t)l*QKVW*DM;                 K = DM;  N = DM;  break;
        case 1: src = Wk + (size_t)l*DM*DM;  dst = g_WqkvH + (size_t)l*QKVW*DM + (size_t)DM*DM; K = DM;  N = DM;  break;
        case 2: src = Wv + (size_t)l*DM*DM;  dst = g_WqkvH + (size_t)l*QKVW*DM + (size_t)2*DM*DM; K = DM; N = DM; break;
        case 3: src = Wo + (size_t)l*DM*DM;  dst = g_WoH + (size_t)l*DM*DM;                     K = DM;  N = DM;  break;
        case 4: src = W1 + (size_t)l*DM*DFF; dst = g_W1H + (size_t)l*DFF*DM;                    K = DM;  N = DFF; break;
        default: src = W2 + (size_t)l*DFF*DM; dst = g_W2H + (size_t)l*DM*DFF;                   K = DFF; N = DM;  break;
    }
    int n0 = blockIdx.x*32, k0 = blockIdx.y*32;
    if (n0 >= N || k0 >= K) return;

    __shared__ float t[32][33];
    int tx = threadIdx.x, ty = threadIdx.y;   // 32 x 8
#pragma unroll
    for (int i = 0; i < 32; i += 8)
        t[ty+i][tx] = src[(size_t)(k0+ty+i)*N + n0+tx];
    __syncthreads();
#pragma unroll
    for (int i = 0; i < 32; i += 8) {
        int n = n0+ty+i, k = k0+tx;
        dst[(size_t)n*K + k] = __float2half_rn(t[tx][ty+i]);
    }
}

// ---------------------------------------------------------------------------
// fp16 mma.sync GEMM (R8-proven core; mainloop untouched).
// MODE 1: relu(out+bias) -> fp16.
// MODE 2: out+bias -> fp16.
// MODE 3: out+bias -> Ph, then last-of-2-CTAs does residual(X)+LN -> X,Xh.
// MODE 4: like 3 but residual from x0[pos(row)] (layer-0 first LN).
// Requires grid.x == 2 and N == 256 for MODE 3/4.
// ---------------------------------------------------------------------------
#define BM 128
#define BN 128
#define BK 64
#define STAGE_BYTES (BM*BK*2 + BN*BK*2)   // 32768
#define GSMEM_TOTAL (3*STAGE_BYTES)       // 98304

template<int MODE>
__global__ void __launch_bounds__(256)
gemm_k(const __half* __restrict__ A,
       const __half* __restrict__ B,
       const float* __restrict__ bias, int KT, int N, int ldc,
       __half* __restrict__ outH,
       const float* __restrict__ lnsc, const float* __restrict__ lnbi,
       int* __restrict__ flags)
{
    extern __shared__ __align__(128) char smem[];
    const uint32_t sb = smem_u32(smem);
    const int tid  = threadIdx.x;
    const int lane = tid & 31, wid = tid >> 5;
    const int wm = wid & 1, wn = wid >> 1;
    const int brow = blockIdx.y * BM;
    const int bcol = blockIdx.x * BN;
    const int KC = KT / BK;
    const int lr = lane & 7, quad = lane >> 3;

    float acc[4][4][4];
#pragma unroll
    for (int a = 0; a < 4; a++)
#pragma unroll
        for (int b = 0; b < 4; b++)
#pragma unroll
            for (int c = 0; c < 4; c++) acc[a][b][c] = 0.f;

    auto load_tile = [&](int i, int st) {
        const uint32_t sa = sb + st*STAGE_BYTES;
        const uint32_t sB = sa + BM*BK*2;
        const int k0 = i * BK;
#pragma unroll
        for (int it = 0; it < 4; it++) {
            int id = it*256 + tid, r = id >> 3, c = id & 7;
            uint32_t sw = r*128 + ((c ^ (r & 7)) << 4);
            cpa16(sa + sw, A + (size_t)(brow + r)*KT + k0 + c*8);
        }
#pragma unroll
        for (int it = 0; it < 4; it++) {
            int id = it*256 + tid, r = id >> 3, c = id & 7;
            uint32_t sw = r*128 + ((c ^ (r & 7)) << 4);
            cpa16(sB + sw, B + (size_t)(bcol + r)*KT + k0 + c*8);
        }
        cpa_commit();
    };

    load_tile(0, 0);
    load_tile(1, 1);

    int rowA[4], rowB[2];
#pragma unroll
    for (int mt = 0; mt < 4; mt++)
        rowA[mt] = wm*64 + mt*16 + lr + ((quad & 1) << 3);
#pragma unroll
    for (int bt = 0; bt < 2; bt++)
        rowB[bt] = wn*32 + bt*16 + lr + ((quad & 2) << 2);
    const int chA = (quad & 2) >> 1;
    const int chB = (quad & 1);

    for (int i = 0; i < KC; i++) {
        if (i + 1 < KC) cpa_wait<1>(); else cpa_wait<0>();
        __syncthreads();
        const uint32_t sa = sb + (i % 3)*STAGE_BYTES;
        const uint32_t sB = sa + BM*BK*2;
#pragma unroll
        for (int ks = 0; ks < 4; ks++) {
            uint32_t af[4][4];
#pragma unroll
            for (int mt = 0; mt < 4; mt++) {
                int ch = ks*2 + chA;
                ldm4(af[mt], sa + rowA[mt]*128 + ((ch ^ (rowA[mt] & 7)) << 4));
            }
            uint32_t bf[2][4];
#pragma unroll
            for (int bt = 0; bt < 2; bt++) {
                int ch = ks*2 + chB;
                ldm4(bf[bt], sB + rowB[bt]*128 + ((ch ^ (rowB[bt] & 7)) << 4));
            }
#pragma unroll
            for (int mt = 0; mt < 4; mt++)
#pragma unroll
                for (int nt = 0; nt < 4; nt++)
                    mma16816(acc[mt][nt], af[mt],
                             bf[nt >> 1][(nt & 1)*2], bf[nt >> 1][(nt & 1)*2 + 1]);
        }
        if (i + 2 < KC) load_tile(i + 2, (i + 2) % 3);
    }

    const int r0 = brow + wm*64 + (lane >> 2);
    const int c0 = bcol + wn*32 + ((lane & 3) << 1);
#pragma unroll
    for (int mt = 0; mt < 4; mt++) {
#pragma unroll
        for (int nt = 0; nt < 4; nt++) {
            int row = r0 + mt*16;
            int col = c0 + nt*8;
            float bv0 = bias[col], bv1 = bias[col + 1];
            float v00 = acc[mt][nt][0] + bv0, v01 = acc[mt][nt][1] + bv1;
            float v10 = acc[mt][nt][2] + bv0, v11 = acc[mt][nt][3] + bv1;
            if (MODE == 1) {
                v00 = fmaxf(v00, 0.f); v01 = fmaxf(v01, 0.f);
                v10 = fmaxf(v10, 0.f); v11 = fmaxf(v11, 0.f);
            }
            *(__half2*)&outH[(size_t)row*ldc + col] =
                __floats2half2_rn(v00, v01);
            *(__half2*)&outH[(size_t)(row+8)*ldc + col] =
                __floats2half2_rn(v10, v11);
        }
    }

    if (MODE >= 3) {
        // Last-of-2-CTAs per row block does residual + LayerNorm.
        __threadfence();
        __shared__ int sflag;
        __syncthreads();
        if (tid == 0) sflag = atomicAdd(&flags[blockIdx.y], 1);
        __syncthreads();
        if (sflag != 1) return;
        __threadfence();

#pragma unroll 1
        for (int i = 0; i < 16; i++) {
            int r = brow + wid + i*8;     // warp handles row r
            const __half* pr = outH + (size_t)r*ldc;
            const float* resb = (MODE == 4) ? (g_x0 + (size_t)g_pos[r]*DM)
                                            : (g_X + (size_t)r*DM);
            float v[8]; float sum = 0.f;
#pragma unroll
            for (int k = 0; k < 8; k++) {
                int c = lane + (k << 5);
                v[k] = resb[c] + __half2float(pr[c]);
                sum += v[k];
            }
#pragma unroll
            for (int o = 16; o; o >>= 1) sum += __shfl_xor_sync(0xffffffffu, sum, o);
            float mu = sum * (1.f / 256.f);
            float sq = 0.f;
#pragma unroll
            for (int k = 0; k < 8; k++) { float d = v[k] - mu; sq = fmaf(d, d, sq); }
#pragma unroll
            for (int o = 16; o; o >>= 1) sq += __shfl_xor_sync(0xffffffffu, sq, o);
            float inv = rsqrtf(sq * (1.f / 256.f) + 1e-5f);
            size_t rb = (size_t)r * DM;
#pragma unroll
            for (int k = 0; k < 8; k++) {
                int c = lane + (k << 5);
                float y = (v[k] - mu) * inv * lnsc[c] + lnbi[c];
                g_X[rb + c]  = y;
                g_Xh[rb + c] = __float2half_rn(y);
            }
        }
        __syncthreads();
        if (tid == 0) flags[blockIdx.y] = 0;   // self-reset for graph replay
    }
}

// ---------------------------------------------------------------------------
// Layer-0 attention via prefix sweep (unchanged).
// ---------------------------------------------------------------------------
__global__ void __launch_bounds__(64)
attn0_kernel(const __half* __restrict__ QKV, __half* __restrict__ Oh)
{
    extern __shared__ float sh[];
    float* Ks = sh;
    float* Vs = sh + NTOK*DHEAD;

    const int h = blockIdx.x;
    const int q = blockIdx.y*64 + threadIdx.x;
    const int t = threadIdx.x;

    const __half2* Q2 = (const __half2*)QKV;
    for (int flat = t; flat < NTOK*16; flat += 64) {
        int j = flat >> 4, c = flat & 15;
        size_t g2 = (size_t)j*(QKVW/2) + h*(DHEAD/2) + c;
        *(float2*)&Ks[(j << 5) + (c << 1)] = __half22float2(Q2[g2 + DM/2]);
        *(float2*)&Vs[(j << 5) + (c << 1)] = __half22float2(Q2[g2 + DM]);
    }

    float qv[DHEAD];
    {
        size_t qb = (size_t)q*(QKVW/2) + h*(DHEAD/2);
#pragma unroll
        for (int c = 0; c < DHEAD/2; c++) {
            float2 f = __half22float2(Q2[qb + c]);
            qv[2*c] = f.x; qv[2*c+1] = f.y;
        }
    }
    __syncthreads();

    float sm = 0.f;
    float acc[DHEAD];
#pragma unroll
    for (int c = 0; c < DHEAD; c++) acc[c] = 0.f;
    const float scale = 0.17677669529663687f;

#pragma unroll 1
    for (int j = 0; j < NTOK - 1; j++) {
        const float* kp = Ks + (j << 5);
        float a0 = 0.f, a1 = 0.f, a2 = 0.f, a3 = 0.f;
#pragma unroll
        for (int c = 0; c < DHEAD; c += 4) {
            a0 = fmaf(qv[c  ], kp[c  ], a0);
            a1 = fmaf(qv[c+1], kp[c+1], a1);
            a2 = fmaf(qv[c+2], kp[c+2], a2);
            a3 = fmaf(qv[c+3], kp[c+3], a3);
        }
        float s = fminf(((a0 + a1) + (a2 + a3)) * scale + g_bias[j], 60.f);
        float e = __expf(s);
        sm += e;
        const float* vp = Vs + (j << 5);
#pragma unroll
        for (int c = 0; c < DHEAD; c++)
            acc[c] = fmaf(e, vp[c], acc[c]);

        if (j >= NOBS - 1 && q <= j) {
            int m = j - (NOBS - 1);
            float inv = 1.f / sm;
            size_t rb = (size_t)(inst_off(m) + q)*DM + h*DHEAD;
#pragma unroll
            for (int c = 0; c < DHEAD; c += 2)
                *(__half2*)&Oh[rb + c] =
                    __floats2half2_rn(acc[c]*inv, acc[c+1]*inv);
        }
    }
}

// ---------------------------------------------------------------------------
// Tensor-core attention (layers 1-2) — unchanged from R8.
// ---------------------------------------------------------------------------
#define QKV_STRIDE 40
#define ATTN_SMEM (3*256*QKV_STRIDE*2 + 256*4)   // 62464

__global__ void __launch_bounds__(256)
attn_tc_kernel(const __half* __restrict__ QKV, __half* __restrict__ Oh)
{
    extern __shared__ __align__(16) char smraw[];
    __half* Qs = (__half*)smraw;
    __half* Ks = Qs + 256*QKV_STRIDE;
    __half* Vs = Ks + 256*QKV_STRIDE;
    float* sbias = (float*)(Vs + 256*QKV_STRIDE);

    const int h = blockIdx.x;
    const int m = blockIdx.y;
    const int p = NOBS + m;
    const int off = inst_off(m);
    const int tid = threadIdx.x;
    const int lane = tid & 31, wq = tid >> 5;

    {
        const uint4* G = (const uint4*)(QKV + (size_t)off*QKVW + h*DHEAD);
        for (int flat = tid; flat < 256*4; flat += 256) {
            int row = flat >> 2, c4 = flat & 3;
            const uint4* gr = G + (size_t)row*96 + c4;
            *(uint4*)(Qs + row*QKV_STRIDE + c4*8) = gr[0];
            *(uint4*)(Ks + row*QKV_STRIDE + c4*8) = gr[32];
            *(uint4*)(Vs + row*QKV_STRIDE + c4*8) = gr[64];
        }
        if (tid < 256) sbias[tid] = (tid < p) ? g_bias[tid] : -1e9f;
    }
    __syncthreads();

    const int r0 = wq * 32;
    if (r0 >= p) return;

    const int lr8  = lane & 7;
    const int c2   = (lane & 3) << 1;
    const int rowg = lane >> 2;

    uint32_t qf[2][2][4];
    {
        int arow = lr8 + 8*((lane >> 3) & 1);
        int acol = 8*(lane >> 4);
#pragma unroll
        for (int mt = 0; mt < 2; mt++)
#pragma unroll
            for (int ks = 0; ks < 2; ks++)
                ldm4(qf[mt][ks],
                     smem_u32(Qs + (r0 + mt*16 + arow)*QKV_STRIDE + ks*16 + acol));
    }

    float oacc[2][4][4];
#pragma unroll
    for (int a = 0; a < 2; a++)
#pragma unroll
        for (int b = 0; b < 4; b++)
#pragma unroll
            for (int c = 0; c < 4; c++) oacc[a][b][c] = 0.f;
    float smr[2][2] = {{0.f, 0.f}, {0.f, 0.f}};

    const float scale = 0.17677669529663687f;
    const int T = (p + 15) >> 4;

    const int krow = lr8 + 8*(lane >> 4);
    const int kcol = 8*((lane >> 3) & 1);
    const int vrow = lr8;
    const int vcol = 8*(lane >> 3);

#pragma unroll 1
    for (int kt = 0; kt < T; kt++) {
        const int kb = kt << 4;

        uint32_t kf[2][4];
#pragma unroll
        for (int ks = 0; ks < 2; ks++)
            ldm4(kf[ks], smem_u32(Ks + (kb + krow)*QKV_STRIDE + ks*16 + kcol));

        uint32_t vfA[4], vfB[4];
        ldm4t(vfA, smem_u32(Vs + (kb + vrow)*QKV_STRIDE + vcol));
        ldm4t(vfB, smem_u32(Vs + (kb + 8 + vrow)*QKV_STRIDE + vcol));

        const int j0 = kb + c2;
        float b00 = sbias[j0],     b01 = sbias[j0 + 1];
        float b10 = sbias[j0 + 8], b11 = sbias[j0 + 9];

#pragma unroll
        for (int mt = 0; mt < 2; mt++) {
            float s0[4] = {0.f, 0.f, 0.f, 0.f};
            float s1[4] = {0.f, 0.f, 0.f, 0.f};
#pragma unroll
            for (int ks = 0; ks < 2; ks++) {
                mma16816(s0, qf[mt][ks], kf[ks][0], kf[ks][1]);
                mma16816(s1, qf[mt][ks], kf[ks][2], kf[ks][3]);
            }
            float e00 = __expf(fminf(s0[0]*scale + b00, 60.f));
            float e01 = __expf(fminf(s0[1]*scale + b01, 60.f));
            float e10 = __expf(fminf(s0[2]*scale + b00, 60.f));
            float e11 = __expf(fminf(s0[3]*scale + b01, 60.f));
            float f00 = __expf(fminf(s1[0]*scale + b10, 60.f));
            float f01 = __expf(fminf(s1[1]*scale + b11, 60.f));
            float f10 = __expf(fminf(s1[2]*scale + b10, 60.f));
            float f11 = __expf(fminf(s1[3]*scale + b11, 60.f));

            smr[mt][0] += (e00 + e01) + (f00 + f01);
            smr[mt][1] += (e10 + e11) + (f10 + f11);

            uint32_t ea[4];
            ea[0] = packh2(e00, e01);
            ea[1] = packh2(e10, e11);
            ea[2] = packh2(f00, f01);
            ea[3] = packh2(f10, f11);

#pragma unroll
            for (int nt = 0; nt < 4; nt++)
                mma16816(oacc[mt][nt], ea, vfA[nt], vfB[nt]);
        }
    }

#pragma unroll
    for (int mt = 0; mt < 2; mt++)
#pragma unroll
        for (int rr = 0; rr < 2; rr++) {
            float s = smr[mt][rr];
            s += __shfl_xor_sync(0xffffffffu, s, 1);
            s += __shfl_xor_sync(0xffffffffu, s, 2);
            smr[mt][rr] = s;
        }

#pragma unroll
    for (int mt = 0; mt < 2; mt++) {
        int ra = r0 + mt*16 + rowg;
        int rb = ra + 8;
        float invA = 1.f / smr[mt][0];
        float invB = 1.f / smr[mt][1];
#pragma unroll
        for (int nt = 0; nt < 4; nt++) {
            int col = h*DHEAD + nt*8 + c2;
            if (ra < p)
                *(__half2*)&Oh[(size_t)(off + ra)*DM + col] =
                    __floats2half2_rn(oacc[mt][nt][0]*invA, oacc[mt][nt][1]*invA);
            if (rb < p)
                *(__half2*)&Oh[(size_t)(off + rb)*DM + col] =
                    __floats2half2_rn(oacc[mt][nt][2]*invB, oacc[mt][nt][3]*invB);
        }
    }
}

// ---------------------------------------------------------------------------
// Layer-3 fused tail v2 (unchanged from R13).
// ---------------------------------------------------------------------------
__global__ void __launch_bounds__(256)
tail_kernel(const __half* __restrict__ QKV,
            const __half* __restrict__ Wq3, const __half* __restrict__ Wo3,
            const __half* __restrict__ W13, const __half* __restrict__ W23,
            const float* __restrict__ bq_, const float* __restrict__ bo_,
            const float* __restrict__ b1_, const float* __restrict__ b2_,
            const float* __restrict__ l1s_, const float* __restrict__ l1b_,
            const float* __restrict__ l2s_, const float* __restrict__ l2b_,
            float* __restrict__ out)
{
    const int m = blockIdx.x;
    const int t = threadIdx.x;
    const int w = t >> 5, lane = t & 31;
    const int p = NOBS + m;
    const int off = inst_off(m);
    const int row = off + NOBS - 1 + m;
    const float scale = 0.17677669529663687f;

    __shared__ float xres[DM];
    __shared__ float xbuf[DM];
    __shared__ float obuf[DM];
    __shared__ float obuf2[DM];
    __shared__ float hbuf[DFF];
    __shared__ float red[8];
    __shared__ float mu_s, var_s;

    xres[t] = g_X[(size_t)row*DM + t];
    __syncthreads();

    // ---- Q-projection: warp w -> outputs w*32..w*32+31 ----
    {
        float xr[8];
#pragma unroll
        for (int j = 0; j < 8; j++) xr[j] = xres[lane*8 + j];
#pragma unroll 4
        for (int i = 0; i < 32; i++) {
            int n = w*32 + i;
            uint4 wv = *(const uint4*)(Wq3 + (size_t)n*DM + lane*8);
            const __half2* h2 = (const __half2*)&wv;
            float s = 0.f;
#pragma unroll
            for (int j = 0; j < 4; j++) {
                float2 f = __half22float2(h2[j]);
                s = fmaf(xr[2*j], f.x, s);
                s = fmaf(xr[2*j+1], f.y, s);
            }
#pragma unroll
            for (int o = 16; o; o >>= 1) s += __shfl_xor_sync(0xffffffffu, s, o);
            if (lane == 0) xbuf[n] = s + bq_[n];
        }
    }
    __syncthreads();

    // ---- attention: warp w = head w ----
    {
        float q[DHEAD];
#pragma unroll
        for (int c = 0; c < DHEAD; c++) q[c] = xbuf[w*DHEAD + c];

        float sm = 0.f;
        float acc[DHEAD];
#pragma unroll
        for (int c = 0; c < DHEAD; c++) acc[c] = 0.f;

        for (int j = lane; j < p; j += 32) {
            const __half2* kr = (const __half2*)(QKV + (size_t)(off + j)*QKVW + DM + w*DHEAD);
            float s = 0.f;
#pragma unroll
            for (int c = 0; c < DHEAD/2; c++) {
                float2 k2 = __half22float2(kr[c]);
                s = fmaf(q[2*c], k2.x, s);
                s = fmaf(q[2*c+1], k2.y, s);
            }
            float e = __expf(fminf(s*scale + g_bias[j], 60.f));
            sm += e;
            const __half2* vr = (const __half2*)(QKV + (size_t)(off + j)*QKVW + 2*DM + w*DHEAD);
#pragma unroll
            for (int c = 0; c < DHEAD/2; c++) {
                float2 v2 = __half22float2(vr[c]);
                acc[2*c]   = fmaf(e, v2.x, acc[2*c]);
                acc[2*c+1] = fmaf(e, v2.y, acc[2*c+1]);
            }
        }
#pragma unroll
        for (int o = 16; o; o >>= 1) sm += __shfl_xor_sync(0xffffffffu, sm, o);
#pragma unroll
        for (int c = 0; c < DHEAD; c++)
#pragma unroll
            for (int o = 16; o; o >>= 1)
                acc[c] += __shfl_xor_sync(0xffffffffu, acc[c], o);
        if (lane < DHEAD/2) {
            float inv = 1.f / sm;
            obuf[w*DHEAD + 2*lane]     = acc[2*lane]*inv;
            obuf[w*DHEAD + 2*lane + 1] = acc[2*lane+1]*inv;
        }
    }
    __syncthreads();

    // ---- O-projection ----
    {
        float xr[8];
#pragma unroll
        for (int j = 0; j < 8; j++) xr[j] = obuf[lane*8 + j];
#pragma unroll 4
        for (int i = 0; i < 32; i++) {
            int n = w*32 + i;
            uint4 wv = *(const uint4*)(Wo3 + (size_t)n*DM + lane*8);
            const __half2* h2 = (const __half2*)&wv;
            float s = 0.f;
#pragma unroll
            for (int j = 0; j < 4; j++) {
                float2 f = __half22float2(h2[j]);
                s = fmaf(xr[2*j], f.x, s);
                s = fmaf(xr[2*j+1], f.y, s);
            }
#pragma unroll
            for (int o = 16; o; o >>= 1) s += __shfl_xor_sync(0xffffffffu, s, o);
            if (lane == 0) obuf2[n] = s + bo_[n];
        }
    }
    __syncthreads();

    // ---- residual + LN1 ----
    float v = xres[t] + obuf2[t];
    {
        float s = v;
#pragma unroll
        for (int o = 16; o; o >>= 1) s += __shfl_xor_sync(0xffffffffu, s, o);
        if (lane == 0) red[w] = s;
        __syncthreads();
        if (t == 0) {
            float x = 0.f;
#pragma unroll
            for (int i = 0; i < 8; i++) x += red[i];
            mu_s = x * (1.f / 256.f);
        }
        __syncthreads();
        float d = v - mu_s;
        float s2 = d*d;
#pragma unroll
        for (int o = 16; o; o >>= 1) s2 += __shfl_xor_sync(0xffffffffu, s2, o);
        if (lane == 0) red[w] = s2;
        __syncthreads();
        if (t == 0) {
            float x = 0.f;
#pragma unroll
            for (int i = 0; i < 8; i++) x += red[i];
            var_s = x * (1.f / 256.f);
        }
        __syncthreads();
        float y = (v - mu_s) * rsqrtf(var_s + 1e-5f) * l1s_[t] + l1b_[t];
        xres[t] = y;
        xbuf[t] = y;
    }
    __syncthreads();

    // ---- FFN1: 1024 outputs, 128 per warp ----
    {
        float xr[8];
#pragma unroll
        for (int j = 0; j < 8; j++) xr[j] = xbuf[lane*8 + j];
#pragma unroll 4
        for (int i = 0; i < 128; i++) {
            int n = w*128 + i;
            uint4 wv = *(const uint4*)(W13 + (size_t)n*DM + lane*8);
            const __half2* h2 = (const __half2*)&wv;
            float s = 0.f;
#pragma unroll
            for (int j = 0; j < 4; j++) {
                float2 f = __half22float2(h2[j]);
                s = fmaf(xr[2*j], f.x, s);
                s = fmaf(xr[2*j+1], f.y, s);
            }
#pragma unroll
            for (int o = 16; o; o >>= 1) s += __shfl_xor_sync(0xffffffffu, s, o);
            if (lane == 0) hbuf[n] = fmaxf(s + b1_[n], 0.f);
        }
    }
    __syncthreads();

    // ---- FFN2: K=1024 ----
    {
        float xr[32];
#pragma unroll
        for (int j = 0; j < 32; j++) xr[j] = hbuf[lane*32 + j];
#pragma unroll 2
        for (int i = 0; i < 32; i++) {
            int n = w*32 + i;
            const uint4* wr = (const uint4*)(W23 + (size_t)n*DFF + lane*32);
            float s = 0.f;
#pragma unroll
            for (int u = 0; u < 4; u++) {
                uint4 wv = wr[u];
                const __half2* h2 = (const __half2*)&wv;
#pragma unroll
                for (int j = 0; j < 4; j++) {
                    float2 f = __half22float2(h2[j]);
                    s = fmaf(xr[u*8 + 2*j], f.x, s);
                    s = fmaf(xr[u*8 + 2*j+1], f.y, s);
                }
            }
#pragma unroll
            for (int o = 16; o; o >>= 1) s += __shfl_xor_sync(0xffffffffu, s, o);
            if (lane == 0) obuf2[n] = s + b2_[n];
        }
    }
    __syncthreads();

    // ---- residual + LN2 -> out ----
    v = xres[t] + obuf2[t];
    {
        float s = v;
#pragma unroll
        for (int o = 16; o; o >>= 1) s += __shfl_xor_sync(0xffffffffu, s, o);
        if (lane == 0) red[w] = s;
        __syncthreads();
        if (t == 0) {
            float x = 0.f;
#pragma unroll
            for (int i = 0; i < 8; i++) x += red[i];
            mu_s = x * (1.f / 256.f);
        }
        __syncthreads();
        float d = v - mu_s;
        float s2 = d*d;
#pragma unroll
        for (int o = 16; o; o >>= 1) s2 += __shfl_xor_sync(0xffffffffu, s2, o);
        if (lane == 0) red[w] = s2;
        __syncthreads();
        if (t == 0) {
            float x = 0.f;
#pragma unroll
            for (int i = 0; i < 8; i++) x += red[i];
            var_s = x * (1.f / 256.f);
        }
        __syncthreads();
        out[(size_t)m*DM + t] =
            (v - mu_s) * rsqrtf(var_s + 1e-5f) * l2s_[t] + l2b_[t];
    }
}

// ---------------------------------------------------------------------------
// Launch
// ---------------------------------------------------------------------------
extern "C" void kernel_launch(void* const* d_in, const int* in_sizes, int n_in,
                              void* d_out, int out_size)
{
    (void)in_sizes; (void)n_in; (void)out_size;
    const float* enc = (const float*)d_in[0];
    const unsigned char* mask = (const unsigned char*)d_in[1];
    const float* Wq = (const float*)d_in[2];
    const float* bq = (const float*)d_in[3];
    const float* Wk = (const float*)d_in[4];
    const float* bk = (const float*)d_in[5];
    const float* Wv = (const float*)d_in[6];
    const float* bv = (const float*)d_in[7];
    const float* Wo = (const float*)d_in[8];
    const float* bo = (const float*)d_in[9];
    const float* l1s = (const float*)d_in[10];
    const float* l1b = (const float*)d_in[11];
    const float* l2s = (const float*)d_in[12];
    const float* l2b = (const float*)d_in[13];
    const float* W1 = (const float*)d_in[14];
    const float* b1 = (const float*)d_in[15];
    const float* W2 = (const float*)d_in[16];
    const float* b2 = (const float*)d_in[17];
    float* out = (float*)d_out;

    float *bqkv;
    __half *Xh, *x0h, *QKVh, *QKV0h, *Oh, *Ph, *Hh;
    __half *WqkvH, *WoH, *W1H, *W2H;
    int *flags;
    cudaGetSymbolAddress((void**)&Xh,    g_Xh);
    cudaGetSymbolAddress((void**)&x0h,   g_x0h);
    cudaGetSymbolAddress((void**)&QKVh,  g_QKVh);
    cudaGetSymbolAddress((void**)&QKV0h, g_QKV0h);
    cudaGetSymbolAddress((void**)&Oh,    g_Oh);
    cudaGetSymbolAddress((void**)&Ph,    g_Ph);
    cudaGetSymbolAddress((void**)&Hh,    g_Hh);
    cudaGetSymbolAddress((void**)&bqkv,  g_bqkv);
    cudaGetSymbolAddress((void**)&WqkvH, g_WqkvH);
    cudaGetSymbolAddress((void**)&WoH,   g_WoH);
    cudaGetSymbolAddress((void**)&W1H,   g_W1H);
    cudaGetSymbolAddress((void**)&W2H,   g_W2H);
    cudaGetSymbolAddress((void**)&flags, g_flags);

    cudaFuncSetAttribute(attn_tc_kernel,
                         cudaFuncAttributeMaxDynamicSharedMemorySize, ATTN_SMEM);
    cudaFuncSetAttribute(attn0_kernel,
                         cudaFuncAttributeMaxDynamicSharedMemorySize, 65536);
    cudaFuncSetAttribute(gemm_k<1>,
                         cudaFuncAttributeMaxDynamicSharedMemorySize, GSMEM_TOTAL);
    cudaFuncSetAttribute(gemm_k<2>,
                         cudaFuncAttributeMaxDynamicSharedMemorySize, GSMEM_TOTAL);
    cudaFuncSetAttribute(gemm_k<3>,
                         cudaFuncAttributeMaxDynamicSharedMemorySize, GSMEM_TOTAL);
    cudaFuncSetAttribute(gemm_k<4>,
                         cudaFuncAttributeMaxDynamicSharedMemorySize, GSMEM_TOTAL);

    init_bias_kernel<<<1, 256>>>(mask);
    init_x0_kernel<<<NTOK, DM>>>(enc);
    concat_bias_kernel<<<NLAYER, DM>>>(bq, bk, bv);
    pos_kernel<<<MINST, 256>>>();
    convw_all_kernel<<<dim3(32, 32, NLAYER*6), dim3(32, 8)>>>(Wq, Wk, Wv, Wo, W1, W2);

    const int RT = RP / BM;                  // 217
    const dim3 g_qkv0(QKVW/BN, NTOK/BM);     // (6, 2)
    const dim3 g_qkv (QKVW/BN, RT);          // (6, 217)
    const dim3 g_kv  (512/BN,  RT);          // (4, 217)
    const dim3 g_o   (DM/BN,   RT);          // (2, 217)
    const dim3 g_ff1 (DFF/BN,  RT);          // (8, 217)

    // ---- layers 0..2: full packed rows, LN fused into O-proj/FFN2 GEMMs ----
    for (int l = 0; l < 3; l++) {
        const __half* wqkv = WqkvH + (size_t)l*QKVW*DM;
        const __half* woh  = WoH  + (size_t)l*DM*DM;
        const __half* w1h  = W1H  + (size_t)l*DFF*DM;
        const __half* w2h  = W2H  + (size_t)l*DM*DFF;
        int* f1 = flags + (2*l + 0)*224;
        int* f2 = flags + (2*l + 1)*224;

        if (l == 0) {
            gemm_k<2><<<g_qkv0, 256, GSMEM_TOTAL>>>(x0h, wqkv, bqkv + l*QKVW,
                DM, QKVW, QKVW, QKV0h, nullptr, nullptr, nullptr);
            attn0_kernel<<<dim3(NHEAD, 4), 64, 65536>>>(QKV0h, Oh);
        } else {
            gemm_k<2><<<g_qkv, 256, GSMEM_TOTAL>>>(Xh, wqkv, bqkv + l*QKVW,
                DM, QKVW, QKVW, QKVh, nullptr, nullptr, nullptr);
            attn_tc_kernel<<<dim3(NHEAD, MINST), 256, ATTN_SMEM>>>(QKVh, Oh);
        }

        if (l == 0)
            gemm_k<4><<<g_o, 256, GSMEM_TOTAL>>>(Oh, woh, bo + l*DM,
                DM, DM, DM, Ph, l1s + l*DM, l1b + l*DM, f1);
        else
            gemm_k<3><<<g_o, 256, GSMEM_TOTAL>>>(Oh, woh, bo + l*DM,
                DM, DM, DM, Ph, l1s + l*DM, l1b + l*DM, f1);

        gemm_k<1><<<g_ff1, 256, GSMEM_TOTAL>>>(Xh, w1h, b1 + l*DFF,
            DM, DFF, DFF, Hh, nullptr, nullptr, nullptr);

        gemm_k<3><<<g_o, 256, GSMEM_TOTAL>>>(Hh, w2h, b2 + l*DM,
            DFF, DM, DM, Ph, l2s + l*DM, l2b + l*DM, f2);
    }

    // ---- layer 3: K/V GEMM on all rows, then one fused per-row tail ----
    {
        const int l = 3;
        const __half* wqkv = WqkvH + (size_t)l*QKVW*DM;

        gemm_k<2><<<g_kv, 256, GSMEM_TOTAL>>>(Xh, wqkv + (size_t)DM*DM,
            bqkv + l*QKVW + DM, DM, 512, QKVW, QKVh + DM,
            nullptr, nullptr, nullptr);

        tail_kernel<<<MINST, 256>>>(QKVh,
            wqkv,
            WoH + (size_t)l*DM*DM,
            W1H + (size_t)l*DFF*DM,
            W2H + (size_t)l*DM*DFF,
            bqkv + l*QKVW, bo + l*DM, b1 + l*DFF, b2 + l*DM,
            l1s + l*DM, l1b + l*DM, l2s + l*DM, l2b + l*DM,
            out);
    }
}

// round 17
// speedup vs baseline: 1.0813x; 1.0813x over previous
#include <cuda_runtime.h>
#include <cuda_fp16.h>
#include <math.h>
#include <stdint.h>

// ---------------------------------------------------------------------------
// Problem constants
// ---------------------------------------------------------------------------
#define MINST 156
#define NTOK  256
#define DM    256
#define DFF   1024
#define NHEAD 8
#define DHEAD 32
#define NOBS  100
#define NLAYER 4

#define RSUM 27690
#define RP   27776            // 217 * 128
#define QKVW (3*DM)           // 768

__device__ __forceinline__ int inst_off(int m) {
    return NOBS*m + (m*(m-1))/2;
}

// ---------------------------------------------------------------------------
// Device-global scratch
// ---------------------------------------------------------------------------
__device__ float  g_X [(size_t)RP*DM];        // fp32 residual stream (packed)
__device__ __half g_Xh[(size_t)RP*DM];        // fp16 copy of X
__device__ __half g_QKVh[(size_t)RP*QKVW];    // fused Q|K|V fp16
__device__ __half g_QKV0h[(size_t)NTOK*QKVW]; // layer-0 compact QKV fp16
__device__ __half g_x0h[(size_t)NTOK*DM];     // layer-0 compact x0 fp16
__device__ __half g_Oh[(size_t)RP*DM];        // attention output fp16
__device__ __half g_Ph[(size_t)RP*DM];        // proj / ffn2 output fp16
__device__ __half g_Hh[(size_t)RP*DFF];       // ffn hidden fp16
__device__ float  g_x0[NTOK*DM];
__device__ float  g_bias[NTOK];
__device__ float  g_bqkv[NLAYER*QKVW];
__device__ int    g_pos[RP];                  // row -> token position (pad: 0)

// fp16 weights, transposed: Wh[N][K]  (row = output col, K-major)
__device__ __half g_WqkvH[NLAYER*(size_t)QKVW*DM];
__device__ __half g_WoH[NLAYER*(size_t)DM*DM];
__device__ __half g_W1H[NLAYER*(size_t)DFF*DM];
__device__ __half g_W2H[NLAYER*(size_t)DM*DFF];

// ---------------------------------------------------------------------------
// PTX helpers
// ---------------------------------------------------------------------------
__device__ __forceinline__ uint32_t smem_u32(const void* p) {
    uint32_t a;
    asm("{ .reg .u64 t; cvta.to.shared.u64 t, %1; cvt.u32.u64 %0, t; }"
        : "=r"(a) : "l"(p));
    return a;
}
__device__ __forceinline__ void cpa16(uint32_t sts, const void* g) {
    asm volatile("cp.async.cg.shared.global [%0], [%1], 16;" :: "r"(sts), "l"(g));
}
__device__ __forceinline__ void cpa_commit() {
    asm volatile("cp.async.commit_group;" ::: "memory");
}
template <int N> __device__ __forceinline__ void cpa_wait() {
    asm volatile("cp.async.wait_group %0;" :: "n"(N) : "memory");
}
__device__ __forceinline__ void ldm4(uint32_t* r, uint32_t a) {
    asm volatile("ldmatrix.sync.aligned.m8n8.x4.shared.b16 {%0,%1,%2,%3}, [%4];"
        : "=r"(r[0]), "=r"(r[1]), "=r"(r[2]), "=r"(r[3]) : "r"(a));
}
__device__ __forceinline__ void ldm4t(uint32_t* r, uint32_t a) {
    asm volatile("ldmatrix.sync.aligned.m8n8.x4.trans.shared.b16 {%0,%1,%2,%3}, [%4];"
        : "=r"(r[0]), "=r"(r[1]), "=r"(r[2]), "=r"(r[3]) : "r"(a));
}
__device__ __forceinline__ void mma16816(float* d, const uint32_t* a,
                                         uint32_t b0, uint32_t b1) {
    asm volatile(
        "mma.sync.aligned.m16n8k16.row.col.f32.f16.f16.f32 "
        "{%0,%1,%2,%3}, {%4,%5,%6,%7}, {%8,%9}, {%0,%1,%2,%3};"
        : "+f"(d[0]), "+f"(d[1]), "+f"(d[2]), "+f"(d[3])
        : "r"(a[0]), "r"(a[1]), "r"(a[2]), "r"(a[3]), "r"(b0), "r"(b1));
}
__device__ __forceinline__ uint32_t packh2(float x, float y) {
    __half2 t = __floats2half2_rn(x, y);
    return *reinterpret_cast<uint32_t*>(&t);
}

// ---------------------------------------------------------------------------
// Init kernels
// ---------------------------------------------------------------------------
__global__ void init_x0_kernel(const float* __restrict__ enc)
{
    int pos = blockIdx.x, c = threadIdx.x;
    float ang = (float)pos * powf(10000.f, -(float)c / 128.f);
    float pe  = (c & 1) ? cosf(ang) : sinf(ang);
    float v = enc[pos*DM + c] + pe;
    g_x0[pos*DM + c]  = v;
    g_x0h[pos*DM + c] = __float2half_rn(v);
}

// Merged setup: block 0 = mask decode; blocks 1..4 = bqkv concat;
// blocks 5..160 = pos table.
__global__ void setup_kernel(const unsigned char* __restrict__ m,
                             const float* __restrict__ bq,
                             const float* __restrict__ bk,
                             const float* __restrict__ bv)
{
    int b = blockIdx.x;
    int t = threadIdx.x;
    if (b == 0) {
        __shared__ int notf32, noti32, anynz;
        if (t == 0) { notf32 = 0; noti32 = 0; anynz = 0; }
        __syncthreads();
        if (t < 64) {
            unsigned int w = ((const unsigned int*)m)[t];
            if (w != 0u && w != 0x3f800000u) atomicOr(&notf32, 1);
            if (w != 0u && w != 1u)          atomicOr(&noti32, 1);
        }
        if (m[t]) atomicOr(&anynz, 1);
        __syncthreads();
        bool mv;
        if (!anynz)        mv = false;
        else if (!notf32)  mv = ((const float*)m)[t] != 0.f;
        else if (!noti32)  mv = ((const int*)m)[t]   != 0;
        else               mv = m[t] != 0;
        g_bias[t] = mv ? 0.f : -1e9f;
    } else if (b <= NLAYER) {
        int l = b - 1;
        g_bqkv[l*QKVW + t]        = bq[l*DM + t];
        g_bqkv[l*QKVW + DM + t]   = bk[l*DM + t];
        g_bqkv[l*QKVW + 2*DM + t] = bv[l*DM + t];
    } else {
        int mm = b - NLAYER - 1;
        int p = NOBS + mm, o = inst_off(mm);
        for (int pos = t; pos < p; pos += 256)
            g_pos[o + pos] = pos;
    }
}

// ---------------------------------------------------------------------------
// Fused weight conversion, all layers & matrices in ONE launch.
// ---------------------------------------------------------------------------
__global__ void convw_all_kernel(
    const float* __restrict__ Wq, const float* __restrict__ Wk,
    const float* __restrict__ Wv, const float* __restrict__ Wo,
    const float* __restrict__ W1, const float* __restrict__ W2)
{
    int z = blockIdx.z;
    int l = z / 6, w = z % 6;
    const float* src; __half* dst; int K, N;
    switch (w) {
        case 0: src = Wq + (size_t)l*DM*DM;  dst = g_WqkvH + (size_t)l*QKVW*DM;                 K = DM;  N = DM;  break;
        case 1: src = Wk + (size_t)l*DM*DM;  dst = g_WqkvH + (size_t)l*QKVW*DM + (size_t)DM*DM; K = DM;  N = DM;  break;
        case 2: src = Wv + (size_t)l*DM*DM;  dst = g_WqkvH + (size_t)l*QKVW*DM + (size_t)2*DM*DM; K = DM; N = DM; break;
        case 3: src = Wo + (size_t)l*DM*DM;  dst = g_WoH + (size_t)l*DM*DM;                     K = DM;  N = DM;  break;
        case 4: src = W1 + (size_t)l*DM*DFF; dst = g_W1H + (size_t)l*DFF*DM;                    K = DM;  N = DFF; break;
        default: src = W2 + (size_t)l*DFF*DM; dst = g_W2H + (size_t)l*DM*DFF;                   K = DFF; N = DM;  break;
    }
    int n0 = blockIdx.x*32, k0 = blockIdx.y*32;
    if (n0 >= N || k0 >= K) return;

    __shared__ float t[32][33];
    int tx = threadIdx.x, ty = threadIdx.y;   // 32 x 8
#pragma unroll
    for (int i = 0; i < 32; i += 8)
        t[ty+i][tx] = src[(size_t)(k0+ty+i)*N + n0+tx];
    __syncthreads();
#pragma unroll
    for (int i = 0; i < 32; i += 8) {
        int n = n0+ty+i, k = k0+tx;
        dst[(size_t)n*K + k] = __float2half_rn(t[tx][ty+i]);
    }
}

// ---------------------------------------------------------------------------
// fp16 mma.sync GEMM (R8-proven core).  BM=128, BN=128, BK=64, 256 thr,
// warp tile 64x32, 3-stage cp.async, fp32 accumulate.  ldc = output stride.
// MODE 1: relu(out+bias) -> fp16.   MODE 2: out+bias -> fp16.
// ---------------------------------------------------------------------------
#define BM 128
#define BN 128
#define BK 64
#define STAGE_BYTES (BM*BK*2 + BN*BK*2)   // 32768
#define GSMEM_TOTAL (3*STAGE_BYTES)       // 98304

template<int MODE>
__global__ void __launch_bounds__(256)
gemm_k(const __half* __restrict__ A,
       const __half* __restrict__ B,
       const float* __restrict__ bias, int KT, int N, int ldc,
       __half* __restrict__ outH)
{
    extern __shared__ __align__(128) char smem[];
    const uint32_t sb = smem_u32(smem);
    const int tid  = threadIdx.x;
    const int lane = tid & 31, wid = tid >> 5;
    const int wm = wid & 1, wn = wid >> 1;
    const int brow = blockIdx.y * BM;
    const int bcol = blockIdx.x * BN;
    const int KC = KT / BK;
    const int lr = lane & 7, quad = lane >> 3;

    float acc[4][4][4];
#pragma unroll
    for (int a = 0; a < 4; a++)
#pragma unroll
        for (int b = 0; b < 4; b++)
#pragma unroll
            for (int c = 0; c < 4; c++) acc[a][b][c] = 0.f;

    auto load_tile = [&](int i, int st) {
        const uint32_t sa = sb + st*STAGE_BYTES;
        const uint32_t sB = sa + BM*BK*2;
        const int k0 = i * BK;
#pragma unroll
        for (int it = 0; it < 4; it++) {
            int id = it*256 + tid, r = id >> 3, c = id & 7;
            uint32_t sw = r*128 + ((c ^ (r & 7)) << 4);
            cpa16(sa + sw, A + (size_t)(brow + r)*KT + k0 + c*8);
        }
#pragma unroll
        for (int it = 0; it < 4; it++) {
            int id = it*256 + tid, r = id >> 3, c = id & 7;
            uint32_t sw = r*128 + ((c ^ (r & 7)) << 4);
            cpa16(sB + sw, B + (size_t)(bcol + r)*KT + k0 + c*8);
        }
        cpa_commit();
    };

    load_tile(0, 0);
    load_tile(1, 1);

    int rowA[4], rowB[2];
#pragma unroll
    for (int mt = 0; mt < 4; mt++)
        rowA[mt] = wm*64 + mt*16 + lr + ((quad & 1) << 3);
#pragma unroll
    for (int bt = 0; bt < 2; bt++)
        rowB[bt] = wn*32 + bt*16 + lr + ((quad & 2) << 2);
    const int chA = (quad & 2) >> 1;
    const int chB = (quad & 1);

    for (int i = 0; i < KC; i++) {
        if (i + 1 < KC) cpa_wait<1>(); else cpa_wait<0>();
        __syncthreads();
        const uint32_t sa = sb + (i % 3)*STAGE_BYTES;
        const uint32_t sB = sa + BM*BK*2;
#pragma unroll
        for (int ks = 0; ks < 4; ks++) {
            uint32_t af[4][4];
#pragma unroll
            for (int mt = 0; mt < 4; mt++) {
                int ch = ks*2 + chA;
                ldm4(af[mt], sa + rowA[mt]*128 + ((ch ^ (rowA[mt] & 7)) << 4));
            }
            uint32_t bf[2][4];
#pragma unroll
            for (int bt = 0; bt < 2; bt++) {
                int ch = ks*2 + chB;
                ldm4(bf[bt], sB + rowB[bt]*128 + ((ch ^ (rowB[bt] & 7)) << 4));
            }
#pragma unroll
            for (int mt = 0; mt < 4; mt++)
#pragma unroll
                for (int nt = 0; nt < 4; nt++)
                    mma16816(acc[mt][nt], af[mt],
                             bf[nt >> 1][(nt & 1)*2], bf[nt >> 1][(nt & 1)*2 + 1]);
        }
        if (i + 2 < KC) load_tile(i + 2, (i + 2) % 3);
    }

    const int r0 = brow + wm*64 + (lane >> 2);
    const int c0 = bcol + wn*32 + ((lane & 3) << 1);
#pragma unroll
    for (int mt = 0; mt < 4; mt++) {
#pragma unroll
        for (int nt = 0; nt < 4; nt++) {
            int row = r0 + mt*16;
            int col = c0 + nt*8;
            float bv0 = bias[col], bv1 = bias[col + 1];
            float v00 = acc[mt][nt][0] + bv0, v01 = acc[mt][nt][1] + bv1;
            float v10 = acc[mt][nt][2] + bv0, v11 = acc[mt][nt][3] + bv1;
            if (MODE == 1) {
                v00 = fmaxf(v00, 0.f); v01 = fmaxf(v01, 0.f);
                v10 = fmaxf(v10, 0.f); v11 = fmaxf(v11, 0.f);
            }
            *(__half2*)&outH[(size_t)row*ldc + col] =
                __floats2half2_rn(v00, v01);
            *(__half2*)&outH[(size_t)(row+8)*ldc + col] =
                __floats2half2_rn(v10, v11);
        }
    }
}

// ---------------------------------------------------------------------------
// Layer-0 attention via prefix sweep.
// ---------------------------------------------------------------------------
__global__ void __launch_bounds__(64)
attn0_kernel(const __half* __restrict__ QKV, __half* __restrict__ Oh)
{
    extern __shared__ float sh[];
    float* Ks = sh;
    float* Vs = sh + NTOK*DHEAD;

    const int h = blockIdx.x;
    const int q = blockIdx.y*64 + threadIdx.x;
    const int t = threadIdx.x;

    const __half2* Q2 = (const __half2*)QKV;
    for (int flat = t; flat < NTOK*16; flat += 64) {
        int j = flat >> 4, c = flat & 15;
        size_t g2 = (size_t)j*(QKVW/2) + h*(DHEAD/2) + c;
        *(float2*)&Ks[(j << 5) + (c << 1)] = __half22float2(Q2[g2 + DM/2]);
        *(float2*)&Vs[(j << 5) + (c << 1)] = __half22float2(Q2[g2 + DM]);
    }

    float qv[DHEAD];
    {
        size_t qb = (size_t)q*(QKVW/2) + h*(DHEAD/2);
#pragma unroll
        for (int c = 0; c < DHEAD/2; c++) {
            float2 f = __half22float2(Q2[qb + c]);
            qv[2*c] = f.x; qv[2*c+1] = f.y;
        }
    }
    __syncthreads();

    float sm = 0.f;
    float acc[DHEAD];
#pragma unroll
    for (int c = 0; c < DHEAD; c++) acc[c] = 0.f;
    const float scale = 0.17677669529663687f;

#pragma unroll 1
    for (int j = 0; j < NTOK - 1; j++) {
        const float* kp = Ks + (j << 5);
        float a0 = 0.f, a1 = 0.f, a2 = 0.f, a3 = 0.f;
#pragma unroll
        for (int c = 0; c < DHEAD; c += 4) {
            a0 = fmaf(qv[c  ], kp[c  ], a0);
            a1 = fmaf(qv[c+1], kp[c+1], a1);
            a2 = fmaf(qv[c+2], kp[c+2], a2);
            a3 = fmaf(qv[c+3], kp[c+3], a3);
        }
        float s = fminf(((a0 + a1) + (a2 + a3)) * scale + g_bias[j], 60.f);
        float e = __expf(s);
        sm += e;
        const float* vp = Vs + (j << 5);
#pragma unroll
        for (int c = 0; c < DHEAD; c++)
            acc[c] = fmaf(e, vp[c], acc[c]);

        if (j >= NOBS - 1 && q <= j) {
            int m = j - (NOBS - 1);
            float inv = 1.f / sm;
            size_t rb = (size_t)(inst_off(m) + q)*DM + h*DHEAD;
#pragma unroll
            for (int c = 0; c < DHEAD; c += 2)
                *(__half2*)&Oh[rb + c] =
                    __floats2half2_rn(acc[c]*inv, acc[c+1]*inv);
        }
    }
}

// ---------------------------------------------------------------------------
// Tensor-core attention (layers 1-2).
// ---------------------------------------------------------------------------
#define QKV_STRIDE 40
#define ATTN_SMEM (3*256*QKV_STRIDE*2 + 256*4)   // 62464

__global__ void __launch_bounds__(256)
attn_tc_kernel(const __half* __restrict__ QKV, __half* __restrict__ Oh)
{
    extern __shared__ __align__(16) char smraw[];
    __half* Qs = (__half*)smraw;
    __half* Ks = Qs + 256*QKV_STRIDE;
    __half* Vs = Ks + 256*QKV_STRIDE;
    float* sbias = (float*)(Vs + 256*QKV_STRIDE);

    const int h = blockIdx.x;
    const int m = blockIdx.y;
    const int p = NOBS + m;
    const int off = inst_off(m);
    const int tid = threadIdx.x;
    const int lane = tid & 31, wq = tid >> 5;

    {
        const uint4* G = (const uint4*)(QKV + (size_t)off*QKVW + h*DHEAD);
        for (int flat = tid; flat < 256*4; flat += 256) {
            int row = flat >> 2, c4 = flat & 3;
            const uint4* gr = G + (size_t)row*96 + c4;
            *(uint4*)(Qs + row*QKV_STRIDE + c4*8) = gr[0];
            *(uint4*)(Ks + row*QKV_STRIDE + c4*8) = gr[32];
            *(uint4*)(Vs + row*QKV_STRIDE + c4*8) = gr[64];
        }
        if (tid < 256) sbias[tid] = (tid < p) ? g_bias[tid] : -1e9f;
    }
    __syncthreads();

    const int r0 = wq * 32;
    if (r0 >= p) return;

    const int lr8  = lane & 7;
    const int c2   = (lane & 3) << 1;
    const int rowg = lane >> 2;

    uint32_t qf[2][2][4];
    {
        int arow = lr8 + 8*((lane >> 3) & 1);
        int acol = 8*(lane >> 4);
#pragma unroll
        for (int mt = 0; mt < 2; mt++)
#pragma unroll
            for (int ks = 0; ks < 2; ks++)
                ldm4(qf[mt][ks],
                     smem_u32(Qs + (r0 + mt*16 + arow)*QKV_STRIDE + ks*16 + acol));
    }

    float oacc[2][4][4];
#pragma unroll
    for (int a = 0; a < 2; a++)
#pragma unroll
        for (int b = 0; b < 4; b++)
#pragma unroll
            for (int c = 0; c < 4; c++) oacc[a][b][c] = 0.f;
    float smr[2][2] = {{0.f, 0.f}, {0.f, 0.f}};

    const float scale = 0.17677669529663687f;
    const int T = (p + 15) >> 4;

    const int krow = lr8 + 8*(lane >> 4);
    const int kcol = 8*((lane >> 3) & 1);
    const int vrow = lr8;
    const int vcol = 8*(lane >> 3);

#pragma unroll 1
    for (int kt = 0; kt < T; kt++) {
        const int kb = kt << 4;

        uint32_t kf[2][4];
#pragma unroll
        for (int ks = 0; ks < 2; ks++)
            ldm4(kf[ks], smem_u32(Ks + (kb + krow)*QKV_STRIDE + ks*16 + kcol));

        uint32_t vfA[4], vfB[4];
        ldm4t(vfA, smem_u32(Vs + (kb + vrow)*QKV_STRIDE + vcol));
        ldm4t(vfB, smem_u32(Vs + (kb + 8 + vrow)*QKV_STRIDE + vcol));

        const int j0 = kb + c2;
        float b00 = sbias[j0],     b01 = sbias[j0 + 1];
        float b10 = sbias[j0 + 8], b11 = sbias[j0 + 9];

#pragma unroll
        for (int mt = 0; mt < 2; mt++) {
            float s0[4] = {0.f, 0.f, 0.f, 0.f};
            float s1[4] = {0.f, 0.f, 0.f, 0.f};
#pragma unroll
            for (int ks = 0; ks < 2; ks++) {
                mma16816(s0, qf[mt][ks], kf[ks][0], kf[ks][1]);
                mma16816(s1, qf[mt][ks], kf[ks][2], kf[ks][3]);
            }
            float e00 = __expf(fminf(s0[0]*scale + b00, 60.f));
            float e01 = __expf(fminf(s0[1]*scale + b01, 60.f));
            float e10 = __expf(fminf(s0[2]*scale + b00, 60.f));
            float e11 = __expf(fminf(s0[3]*scale + b01, 60.f));
            float f00 = __expf(fminf(s1[0]*scale + b10, 60.f));
            float f01 = __expf(fminf(s1[1]*scale + b11, 60.f));
            float f10 = __expf(fminf(s1[2]*scale + b10, 60.f));
            float f11 = __expf(fminf(s1[3]*scale + b11, 60.f));

            smr[mt][0] += (e00 + e01) + (f00 + f01);
            smr[mt][1] += (e10 + e11) + (f10 + f11);

            uint32_t ea[4];
            ea[0] = packh2(e00, e01);
            ea[1] = packh2(e10, e11);
            ea[2] = packh2(f00, f01);
            ea[3] = packh2(f10, f11);

#pragma unroll
            for (int nt = 0; nt < 4; nt++)
                mma16816(oacc[mt][nt], ea, vfA[nt], vfB[nt]);
        }
    }

#pragma unroll
    for (int mt = 0; mt < 2; mt++)
#pragma unroll
        for (int rr = 0; rr < 2; rr++) {
            float s = smr[mt][rr];
            s += __shfl_xor_sync(0xffffffffu, s, 1);
            s += __shfl_xor_sync(0xffffffffu, s, 2);
            smr[mt][rr] = s;
        }

#pragma unroll
    for (int mt = 0; mt < 2; mt++) {
        int ra = r0 + mt*16 + rowg;
        int rb = ra + 8;
        float invA = 1.f / smr[mt][0];
        float invB = 1.f / smr[mt][1];
#pragma unroll
        for (int nt = 0; nt < 4; nt++) {
            int col = h*DHEAD + nt*8 + c2;
            if (ra < p)
                *(__half2*)&Oh[(size_t)(off + ra)*DM + col] =
                    __floats2half2_rn(oacc[mt][nt][0]*invA, oacc[mt][nt][1]*invA);
            if (rb < p)
                *(__half2*)&Oh[(size_t)(off + rb)*DM + col] =
                    __floats2half2_rn(oacc[mt][nt][2]*invB, oacc[mt][nt][3]*invB);
        }
    }
}

// ---------------------------------------------------------------------------
// X = LayerNorm(res + Ph); writes X fp32 + Xh fp16.
// L0=1: residual read from x0[pos(row)].
// ---------------------------------------------------------------------------
template<int L0>
__global__ void __launch_bounds__(256)
add_ln_kernel(float* __restrict__ X, const __half* __restrict__ P,
              const float* __restrict__ sc, const float* __restrict__ bi)
{
    int r    = blockIdx.x * 8 + (threadIdx.x >> 5);
    int lane = threadIdx.x & 31;
    const float* resb = L0 ? (g_x0 + (size_t)g_pos[r]*DM)
                           : (X + (size_t)r*DM);
    const __half* pr = P + (size_t)r * DM;

    float v[8]; float sum = 0.f;
#pragma unroll
    for (int k = 0; k < 8; k++) {
        int c = lane + (k << 5);
        v[k] = resb[c] + __half2float(pr[c]);
        sum += v[k];
    }
#pragma unroll
    for (int o = 16; o; o >>= 1) sum += __shfl_xor_sync(0xffffffffu, sum, o);
    float mu = sum * (1.f / 256.f);

    float sq = 0.f;
#pragma unroll
    for (int k = 0; k < 8; k++) { float d = v[k] - mu; sq = fmaf(d, d, sq); }
#pragma unroll
    for (int o = 16; o; o >>= 1) sq += __shfl_xor_sync(0xffffffffu, sq, o);

    float inv = rsqrtf(sq * (1.f / 256.f) + 1e-5f);
    size_t rb = (size_t)r * DM;
#pragma unroll
    for (int k = 0; k < 8; k++) {
        int c = lane + (k << 5);
        float y = (v[k] - mu) * inv * sc[c] + bi[c];
        X[rb + c]    = y;
        g_Xh[rb + c] = __float2half_rn(y);
    }
}

// ---------------------------------------------------------------------------
// Layer-3 fused tail v2: one CTA per output row.  Warp-per-output matvecs
// on transposed [N][K] weights.
// ---------------------------------------------------------------------------
__global__ void __launch_bounds__(256)
tail_kernel(const __half* __restrict__ QKV,
            const __half* __restrict__ Wq3, const __half* __restrict__ Wo3,
            const __half* __restrict__ W13, const __half* __restrict__ W23,
            const float* __restrict__ bq_, const float* __restrict__ bo_,
            const float* __restrict__ b1_, const float* __restrict__ b2_,
            const float* __restrict__ l1s_, const float* __restrict__ l1b_,
            const float* __restrict__ l2s_, const float* __restrict__ l2b_,
            float* __restrict__ out)
{
    const int m = blockIdx.x;
    const int t = threadIdx.x;
    const int w = t >> 5, lane = t & 31;
    const int p = NOBS + m;
    const int off = inst_off(m);
    const int row = off + NOBS - 1 + m;
    const float scale = 0.17677669529663687f;

    __shared__ float xres[DM];
    __shared__ float xbuf[DM];
    __shared__ float obuf[DM];
    __shared__ float obuf2[DM];
    __shared__ float hbuf[DFF];
    __shared__ float red[8];
    __shared__ float mu_s, var_s;

    xres[t] = g_X[(size_t)row*DM + t];
    __syncthreads();

    // ---- Q-projection: warp w -> outputs w*32..w*32+31 ----
    {
        float xr[8];
#pragma unroll
        for (int j = 0; j < 8; j++) xr[j] = xres[lane*8 + j];
#pragma unroll 4
        for (int i = 0; i < 32; i++) {
            int n = w*32 + i;
            uint4 wv = *(const uint4*)(Wq3 + (size_t)n*DM + lane*8);
            const __half2* h2 = (const __half2*)&wv;
            float s = 0.f;
#pragma unroll
            for (int j = 0; j < 4; j++) {
                float2 f = __half22float2(h2[j]);
                s = fmaf(xr[2*j], f.x, s);
                s = fmaf(xr[2*j+1], f.y, s);
            }
#pragma unroll
            for (int o = 16; o; o >>= 1) s += __shfl_xor_sync(0xffffffffu, s, o);
            if (lane == 0) xbuf[n] = s + bq_[n];
        }
    }
    __syncthreads();

    // ---- attention: warp w = head w ----
    {
        float q[DHEAD];
#pragma unroll
        for (int c = 0; c < DHEAD; c++) q[c] = xbuf[w*DHEAD + c];

        float sm = 0.f;
        float acc[DHEAD];
#pragma unroll
        for (int c = 0; c < DHEAD; c++) acc[c] = 0.f;

        for (int j = lane; j < p; j += 32) {
            const __half2* kr = (const __half2*)(QKV + (size_t)(off + j)*QKVW + DM + w*DHEAD);
            float s = 0.f;
#pragma unroll
            for (int c = 0; c < DHEAD/2; c++) {
                float2 k2 = __half22float2(kr[c]);
                s = fmaf(q[2*c], k2.x, s);
                s = fmaf(q[2*c+1], k2.y, s);
            }
            float e = __expf(fminf(s*scale + g_bias[j], 60.f));
            sm += e;
            const __half2* vr = (const __half2*)(QKV + (size_t)(off + j)*QKVW + 2*DM + w*DHEAD);
#pragma unroll
            for (int c = 0; c < DHEAD/2; c++) {
                float2 v2 = __half22float2(vr[c]);
                acc[2*c]   = fmaf(e, v2.x, acc[2*c]);
                acc[2*c+1] = fmaf(e, v2.y, acc[2*c+1]);
            }
        }
#pragma unroll
        for (int o = 16; o; o >>= 1) sm += __shfl_xor_sync(0xffffffffu, sm, o);
#pragma unroll
        for (int c = 0; c < DHEAD; c++)
#pragma unroll
            for (int o = 16; o; o >>= 1)
                acc[c] += __shfl_xor_sync(0xffffffffu, acc[c], o);
        if (lane < DHEAD/2) {
            float inv = 1.f / sm;
            obuf[w*DHEAD + 2*lane]     = acc[2*lane]*inv;
            obuf[w*DHEAD + 2*lane + 1] = acc[2*lane+1]*inv;
        }
    }
    __syncthreads();

    // ---- O-projection ----
    {
        float xr[8];
#pragma unroll
        for (int j = 0; j < 8; j++) xr[j] = obuf[lane*8 + j];
#pragma unroll 4
        for (int i = 0; i < 32; i++) {
            int n = w*32 + i;
            uint4 wv = *(const uint4*)(Wo3 + (size_t)n*DM + lane*8);
            const __half2* h2 = (const __half2*)&wv;
            float s = 0.f;
#pragma unroll
            for (int j = 0; j < 4; j++) {
                float2 f = __half22float2(h2[j]);
                s = fmaf(xr[2*j], f.x, s);
                s = fmaf(xr[2*j+1], f.y, s);
            }
#pragma unroll
            for (int o = 16; o; o >>= 1) s += __shfl_xor_sync(0xffffffffu, s, o);
            if (lane == 0) obuf2[n] = s + bo_[n];
        }
    }
    __syncthreads();

    // ---- residual + LN1 ----
    float v = xres[t] + obuf2[t];
    {
        float s = v;
#pragma unroll
        for (int o = 16; o; o >>= 1) s += __shfl_xor_sync(0xffffffffu, s, o);
        if (lane == 0) red[w] = s;
        __syncthreads();
        if (t == 0) {
            float x = 0.f;
#pragma unroll
            for (int i = 0; i < 8; i++) x += red[i];
            mu_s = x * (1.f / 256.f);
        }
        __syncthreads();
        float d = v - mu_s;
        float s2 = d*d;
#pragma unroll
        for (int o = 16; o; o >>= 1) s2 += __shfl_xor_sync(0xffffffffu, s2, o);
        if (lane == 0) red[w] = s2;
        __syncthreads();
        if (t == 0) {
            float x = 0.f;
#pragma unroll
            for (int i = 0; i < 8; i++) x += red[i];
            var_s = x * (1.f / 256.f);
        }
        __syncthreads();
        float y = (v - mu_s) * rsqrtf(var_s + 1e-5f) * l1s_[t] + l1b_[t];
        xres[t] = y;
        xbuf[t] = y;
    }
    __syncthreads();

    // ---- FFN1: 1024 outputs, 128 per warp ----
    {
        float xr[8];
#pragma unroll
        for (int j = 0; j < 8; j++) xr[j] = xbuf[lane*8 + j];
#pragma unroll 4
        for (int i = 0; i < 128; i++) {
            int n = w*128 + i;
            uint4 wv = *(const uint4*)(W13 + (size_t)n*DM + lane*8);
            const __half2* h2 = (const __half2*)&wv;
            float s = 0.f;
#pragma unroll
            for (int j = 0; j < 4; j++) {
                float2 f = __half22float2(h2[j]);
                s = fmaf(xr[2*j], f.x, s);
                s = fmaf(xr[2*j+1], f.y, s);
            }
#pragma unroll
            for (int o = 16; o; o >>= 1) s += __shfl_xor_sync(0xffffffffu, s, o);
            if (lane == 0) hbuf[n] = fmaxf(s + b1_[n], 0.f);
        }
    }
    __syncthreads();

    // ---- FFN2: K=1024 ----
    {
        float xr[32];
#pragma unroll
        for (int j = 0; j < 32; j++) xr[j] = hbuf[lane*32 + j];
#pragma unroll 2
        for (int i = 0; i < 32; i++) {
            int n = w*32 + i;
            const uint4* wr = (const uint4*)(W23 + (size_t)n*DFF + lane*32);
            float s = 0.f;
#pragma unroll
            for (int u = 0; u < 4; u++) {
                uint4 wv = wr[u];
                const __half2* h2 = (const __half2*)&wv;
#pragma unroll
                for (int j = 0; j < 4; j++) {
                    float2 f = __half22float2(h2[j]);
                    s = fmaf(xr[u*8 + 2*j], f.x, s);
                    s = fmaf(xr[u*8 + 2*j+1], f.y, s);
                }
            }
#pragma unroll
            for (int o = 16; o; o >>= 1) s += __shfl_xor_sync(0xffffffffu, s, o);
            if (lane == 0) obuf2[n] = s + b2_[n];
        }
    }
    __syncthreads();

    // ---- residual + LN2 -> out ----
    v = xres[t] + obuf2[t];
    {
        float s = v;
#pragma unroll
        for (int o = 16; o; o >>= 1) s += __shfl_xor_sync(0xffffffffu, s, o);
        if (lane == 0) red[w] = s;
        __syncthreads();
        if (t == 0) {
            float x = 0.f;
#pragma unroll
            for (int i = 0; i < 8; i++) x += red[i];
            mu_s = x * (1.f / 256.f);
        }
        __syncthreads();
        float d = v - mu_s;
        float s2 = d*d;
#pragma unroll
        for (int o = 16; o; o >>= 1) s2 += __shfl_xor_sync(0xffffffffu, s2, o);
        if (lane == 0) red[w] = s2;
        __syncthreads();
        if (t == 0) {
            float x = 0.f;
#pragma unroll
            for (int i = 0; i < 8; i++) x += red[i];
            var_s = x * (1.f / 256.f);
        }
        __syncthreads();
        out[(size_t)m*DM + t] =
            (v - mu_s) * rsqrtf(var_s + 1e-5f) * l2s_[t] + l2b_[t];
    }
}

// ---------------------------------------------------------------------------
// Launch
// ---------------------------------------------------------------------------
extern "C" void kernel_launch(void* const* d_in, const int* in_sizes, int n_in,
                              void* d_out, int out_size)
{
    (void)in_sizes; (void)n_in; (void)out_size;
    const float* enc = (const float*)d_in[0];
    const unsigned char* mask = (const unsigned char*)d_in[1];
    const float* Wq = (const float*)d_in[2];
    const float* bq = (const float*)d_in[3];
    const float* Wk = (const float*)d_in[4];
    const float* bk = (const float*)d_in[5];
    const float* Wv = (const float*)d_in[6];
    const float* bv = (const float*)d_in[7];
    const float* Wo = (const float*)d_in[8];
    const float* bo = (const float*)d_in[9];
    const float* l1s = (const float*)d_in[10];
    const float* l1b = (const float*)d_in[11];
    const float* l2s = (const float*)d_in[12];
    const float* l2b = (const float*)d_in[13];
    const float* W1 = (const float*)d_in[14];
    const float* b1 = (const float*)d_in[15];
    const float* W2 = (const float*)d_in[16];
    const float* b2 = (const float*)d_in[17];
    float* out = (float*)d_out;

    float *X, *bqkv;
    __half *Xh, *x0h, *QKVh, *QKV0h, *Oh, *Ph, *Hh;
    __half *WqkvH, *WoH, *W1H, *W2H;
    cudaGetSymbolAddress((void**)&X,     g_X);
    cudaGetSymbolAddress((void**)&Xh,    g_Xh);
    cudaGetSymbolAddress((void**)&x0h,   g_x0h);
    cudaGetSymbolAddress((void**)&QKVh,  g_QKVh);
    cudaGetSymbolAddress((void**)&QKV0h, g_QKV0h);
    cudaGetSymbolAddress((void**)&Oh,    g_Oh);
    cudaGetSymbolAddress((void**)&Ph,    g_Ph);
    cudaGetSymbolAddress((void**)&Hh,    g_Hh);
    cudaGetSymbolAddress((void**)&bqkv,  g_bqkv);
    cudaGetSymbolAddress((void**)&WqkvH, g_WqkvH);
    cudaGetSymbolAddress((void**)&WoH,   g_WoH);
    cudaGetSymbolAddress((void**)&W1H,   g_W1H);
    cudaGetSymbolAddress((void**)&W2H,   g_W2H);

    cudaFuncSetAttribute(attn_tc_kernel,
                         cudaFuncAttributeMaxDynamicSharedMemorySize, ATTN_SMEM);
    cudaFuncSetAttribute(attn0_kernel,
                         cudaFuncAttributeMaxDynamicSharedMemorySize, 65536);
    cudaFuncSetAttribute(gemm_k<1>,
                         cudaFuncAttributeMaxDynamicSharedMemorySize, GSMEM_TOTAL);
    cudaFuncSetAttribute(gemm_k<2>,
                         cudaFuncAttributeMaxDynamicSharedMemorySize, GSMEM_TOTAL);

    setup_kernel<<<1 + NLAYER + MINST, 256>>>(mask, bq, bk, bv);
    init_x0_kernel<<<NTOK, DM>>>(enc);
    convw_all_kernel<<<dim3(32, 32, NLAYER*6), dim3(32, 8)>>>(Wq, Wk, Wv, Wo, W1, W2);

    const int RT = RP / BM;                  // 217
    const dim3 g_qkv0(QKVW/BN, NTOK/BM);     // (6, 2)
    const dim3 g_qkv (QKVW/BN, RT);          // (6, 217)
    const dim3 g_kv  (512/BN,  RT);          // (4, 217)
    const dim3 g_o   (DM/BN,   RT);          // (2, 217)
    const dim3 g_ff1 (DFF/BN,  RT);          // (8, 217)

    // ---- layers 0..2: full packed rows ----
    for (int l = 0; l < 3; l++) {
        const __half* wqkv = WqkvH + (size_t)l*QKVW*DM;
        const __half* woh  = WoH  + (size_t)l*DM*DM;
        const __half* w1h  = W1H  + (size_t)l*DFF*DM;
        const __half* w2h  = W2H  + (size_t)l*DM*DFF;

        if (l == 0) {
            gemm_k<2><<<g_qkv0, 256, GSMEM_TOTAL>>>(x0h, wqkv, bqkv + l*QKVW,
                DM, QKVW, QKVW, QKV0h);
            attn0_kernel<<<dim3(NHEAD, 4), 64, 65536>>>(QKV0h, Oh);
        } else {
            gemm_k<2><<<g_qkv, 256, GSMEM_TOTAL>>>(Xh, wqkv, bqkv + l*QKVW,
                DM, QKVW, QKVW, QKVh);
            attn_tc_kernel<<<dim3(NHEAD, MINST), 256, ATTN_SMEM>>>(QKVh, Oh);
        }

        gemm_k<2><<<g_o, 256, GSMEM_TOTAL>>>(Oh, woh, bo + l*DM,
            DM, DM, DM, Ph);
        if (l == 0)
            add_ln_kernel<1><<<RP/8, 256>>>(X, Ph, l1s + l*DM, l1b + l*DM);
        else
            add_ln_kernel<0><<<RP/8, 256>>>(X, Ph, l1s + l*DM, l1b + l*DM);

        gemm_k<1><<<g_ff1, 256, GSMEM_TOTAL>>>(Xh, w1h, b1 + l*DFF,
            DM, DFF, DFF, Hh);
        gemm_k<2><<<g_o, 256, GSMEM_TOTAL>>>(Hh, w2h, b2 + l*DM,
            DFF, DM, DM, Ph);
        add_ln_kernel<0><<<RP/8, 256>>>(X, Ph, l2s + l*DM, l2b + l*DM);
    }

    // ---- layer 3: K/V GEMM on all rows, then one fused per-row tail ----
    {
        const int l = 3;
        const __half* wqkv = WqkvH + (size_t)l*QKVW*DM;

        gemm_k<2><<<g_kv, 256, GSMEM_TOTAL>>>(Xh, wqkv + (size_t)DM*DM,
            bqkv + l*QKVW + DM, DM, 512, QKVW, QKVh + DM);

        tail_kernel<<<MINST, 256>>>(QKVh,
            wqkv,
            WoH + (size_t)l*DM*DM,
            W1H + (size_t)l*DFF*DM,
            W2H + (size_t)l*DM*DFF,
            bqkv + l*QKVW, bo + l*DM, b1 + l*DFF, b2 + l*DM,
            l1s + l*DM, l1b + l*DM, l2s + l*DM, l2b + l*DM,
            out);
    }
}